// round 8
// baseline (speedup 1.0000x reference)
#include <cuda_runtime.h>
#include <math.h>

// x, x_r : (1, 3, 32, 512, 512) float32
// size=64 -> hc=wc=32 ; 16x16 patches per frame ; t=32
// patch mean = sum(|x - x_r|) / (2*3072) ; out = log(mean_t(max_patches))
// Deferred scaling: out = log( sum_t(max_p sum|dx|) / (32*6144) )
//
// One patch per CTA (8192 CTAs x 256 threads). Each thread owns ONE
// (row, col4) slot of the 32x32 patch and reads it for all 3 channels of
// both tensors: 6 independent LDG.128 issued back-to-back (ordered volatile
// asm) BEFORE any arithmetic -> MLP_eff = 6 per thread instead of the
// register-starved ~2 of the previous build.

#define T_DIM 32
#define NPATCH 8192
#define HW 512
#define TSTRIDE (512u * 512u)
#define CSTRIDE (32u * 512u * 512u)

__device__ int          g_frame_max[T_DIM];   // float bits; >=0 so int order == float order
__device__ unsigned int g_done_count;

__device__ __forceinline__ float4 ldcs4(const float* p) {
    float4 v;
    asm volatile("ld.global.cs.v4.f32 {%0,%1,%2,%3}, [%4];"
                 : "=f"(v.x), "=f"(v.y), "=f"(v.z), "=f"(v.w) : "l"(p));
    return v;
}

__global__ __launch_bounds__(256, 6)
void patch_loss_kernel(const float* __restrict__ x, const float* __restrict__ xr,
                       float* __restrict__ out) {
    const int p  = blockIdx.x;          // t*256 + ph*16 + pw
    const int t  = p >> 8;
    const int ph = (p >> 4) & 15;
    const int pw = p & 15;

    // thread slot: row = tid/8 (0..31), col4 = (tid%8)*4 ; same slot for all 3 channels
    const int row = threadIdx.x >> 3;
    const int col = (threadIdx.x & 7) << 2;
    const size_t base = (size_t)t * TSTRIDE
                      + (size_t)(ph * 32 + row) * HW
                      + (size_t)(pw * 32 + col);

    const float* px = x  + base;
    const float* pr = xr + base;

    // ---- issue all 6 independent 16B loads before any math (MLP = 6) ----
    const float4 a0 = ldcs4(px);
    const float4 a1 = ldcs4(px + CSTRIDE);
    const float4 a2 = ldcs4(px + 2u * CSTRIDE);
    const float4 b0 = ldcs4(pr);
    const float4 b1 = ldcs4(pr + CSTRIDE);
    const float4 b2 = ldcs4(pr + 2u * CSTRIDE);

    float acc = fabsf(a0.x - b0.x) + fabsf(a0.y - b0.y)
              + fabsf(a0.z - b0.z) + fabsf(a0.w - b0.w);
    acc      += fabsf(a1.x - b1.x) + fabsf(a1.y - b1.y)
              + fabsf(a1.z - b1.z) + fabsf(a1.w - b1.w);
    acc      += fabsf(a2.x - b2.x) + fabsf(a2.y - b2.y)
              + fabsf(a2.z - b2.z) + fabsf(a2.w - b2.w);

    // intra-warp reduce
    #pragma unroll
    for (int o = 16; o > 0; o >>= 1)
        acc += __shfl_xor_sync(0xFFFFFFFFu, acc, o);

    __shared__ float s[8];
    if ((threadIdx.x & 31) == 0) s[threadIdx.x >> 5] = acc;
    __syncthreads();

    if (threadIdx.x < 32) {
        const int lane = threadIdx.x;
        float v = (lane < 8) ? s[lane] : 0.0f;
        #pragma unroll
        for (int o = 16; o > 0; o >>= 1)
            v += __shfl_xor_sync(0xFFFFFFFFu, v, o);   // lane-uniform block total

        unsigned int prev = 0;
        if (lane == 0) {
            // REDG max (no return), L2-side
            asm volatile("red.global.max.s32 [%0], %1;"
                         :: "l"(&g_frame_max[t]), "r"(__float_as_int(v)) : "memory");
            // release-ordered ticket: orders the red above, no L1-flushing fence
            asm volatile("atom.release.gpu.global.add.u32 %0, [%1], 1;"
                         : "=r"(prev) : "l"(&g_done_count) : "memory");
        }
        prev = __shfl_sync(0xFFFFFFFFu, prev, 0);

        if (prev == NPATCH - 1) {                       // last CTA: finalize
            asm volatile("fence.acq_rel.gpu;" ::: "memory");
            float sum = __int_as_float(__ldcg(&g_frame_max[lane]));
            #pragma unroll
            for (int o = 16; o > 0; o >>= 1)
                sum += __shfl_xor_sync(0xFFFFFFFFu, sum, o);
            if (lane == 0) {
                *out = logf(sum / (32.0f * 6144.0f));
                g_done_count = 0u;                      // re-arm for next replay
            }
            __syncwarp();
            g_frame_max[lane] = 0;                      // re-arm (after reads)
        }
    }
}

extern "C" void kernel_launch(void* const* d_in, const int* in_sizes, int n_in,
                              void* d_out, int out_size) {
    const float* x  = (const float*)d_in[0];
    const float* xr = (const float*)d_in[1];
    patch_loss_kernel<<<NPATCH, 256>>>(x, xr, (float*)d_out);
}

// round 9
// speedup vs baseline: 1.0199x; 1.0199x over previous
#include <cuda_runtime.h>
#include <math.h>

// x, x_r : (1, 3, 32, 512, 512) float32
// size=64 -> hc=wc=32 ; 16x16 patches per frame ; t=32
// patch mean = sum(|x - x_r|) / (2*3072) ; out = log(mean_t(max_patches))
// Deferred scaling: out = log( sum_t(max_p sum|dx|) / (32*6144) )
//
// Persistent single-wave layout: 1024 CTAs x 256 threads, grid-stride over
// patches -> EXACTLY 8 patches per CTA (8192 = 1024*8). 1024 CTAs at occ 8
// is a single wave on 148/152 SMs: no wave transitions, no partial tail.
// Inner body is the proven R5 serial-pair loop (steady MLP~2; front-batching
// regressed via cross-CTA L1tex-queue spread). No per-patch block barrier:
// per-warp partials -> smem, ONE __syncthreads at the end.

#define T_DIM 32
#define NPATCH 8192
#define NCTA 1024
#define PPB 8                    // patches per CTA
#define HW 512
#define TSTRIDE (512u * 512u)
#define CSTRIDE (32u * 512u * 512u)

__device__ int          g_frame_max[T_DIM];   // float bits; >=0 so int order == float order
__device__ unsigned int g_done_count;

__device__ __forceinline__ float4 ldcs4(const float* p) {
    float4 v;
    asm volatile("ld.global.cs.v4.f32 {%0,%1,%2,%3}, [%4];"
                 : "=f"(v.x), "=f"(v.y), "=f"(v.z), "=f"(v.w) : "l"(p));
    return v;
}

__global__ __launch_bounds__(256, 8)
void patch_loss_kernel(const float* __restrict__ x, const float* __restrict__ xr,
                       float* __restrict__ out) {
    const int wid  = threadIdx.x >> 5;
    const int lane = threadIdx.x & 31;

    // fixed per-thread slot inside any 32x32 patch: row = tid/8, col4 = (tid%8)*4
    const int row = threadIdx.x >> 3;
    const int col = (threadIdx.x & 7) << 2;

    __shared__ float s[PPB][8];    // [patch-within-CTA][warp] partials

    #pragma unroll
    for (int k = 0; k < PPB; ++k) {
        const int p  = blockIdx.x + k * NCTA;   // t*256 + ph*16 + pw
        const int t  = p >> 8;
        const int ph = (p >> 4) & 15;
        const int pw = p & 15;

        const size_t base = (size_t)t * TSTRIDE
                          + (size_t)(ph * 32 + row) * HW
                          + (size_t)(pw * 32 + col);

        float acc = 0.0f;
        #pragma unroll
        for (int c = 0; c < 3; ++c) {           // serial pairs: steady MLP, no burst
            const float4 a = ldcs4(x  + base + (size_t)c * CSTRIDE);
            const float4 b = ldcs4(xr + base + (size_t)c * CSTRIDE);
            acc += fabsf(a.x - b.x) + fabsf(a.y - b.y)
                 + fabsf(a.z - b.z) + fabsf(a.w - b.w);
        }

        #pragma unroll
        for (int o = 16; o > 0; o >>= 1)
            acc += __shfl_xor_sync(0xFFFFFFFFu, acc, o);

        if (lane == 0) s[k][wid] = acc;
        // no block barrier here: next patch's loads stream immediately
    }

    __syncthreads();               // one barrier per CTA

    if (wid == 0) {
        if (lane < PPB) {          // lane i finishes patch i of this CTA
            const int p = blockIdx.x + lane * NCTA;
            float v = 0.0f;
            #pragma unroll
            for (int w = 0; w < 8; ++w) v += s[lane][w];
            asm volatile("red.global.max.s32 [%0], %1;"
                         :: "l"(&g_frame_max[p >> 8]), "r"(__float_as_int(v)) : "memory");
        }
        __syncwarp();

        unsigned int prev = 0;
        if (lane == 0) {
            __threadfence();       // make lanes 0..7's REDGs cumulatively visible
            asm volatile("atom.release.gpu.global.add.u32 %0, [%1], 1;"
                         : "=r"(prev) : "l"(&g_done_count) : "memory");
        }
        prev = __shfl_sync(0xFFFFFFFFu, prev, 0);

        if (prev == NCTA - 1) {    // last CTA: finalize
            asm volatile("fence.acq_rel.gpu;" ::: "memory");
            float sum = __int_as_float(__ldcg(&g_frame_max[lane]));
            #pragma unroll
            for (int o = 16; o > 0; o >>= 1)
                sum += __shfl_xor_sync(0xFFFFFFFFu, sum, o);
            if (lane == 0) {
                *out = logf(sum / (32.0f * 6144.0f));
                g_done_count = 0u;                      // re-arm for next replay
            }
            __syncwarp();
            g_frame_max[lane] = 0;                      // re-arm (after reads)
        }
    }
}

extern "C" void kernel_launch(void* const* d_in, const int* in_sizes, int n_in,
                              void* d_out, int out_size) {
    const float* x  = (const float*)d_in[0];
    const float* xr = (const float*)d_in[1];
    patch_loss_kernel<<<NCTA, 256>>>(x, xr, (float*)d_out);
}